// round 11
// baseline (speedup 1.0000x reference)
#include <cuda_runtime.h>
#include <math.h>

#define NN 4096
#define EE 1024
#define HH 16
#define VV 32
#define LL 6
#define HV 512
#define E2 2048

typedef unsigned long long ull;

// ---------------- scratch (static device globals; no allocations) -------------
__device__ float g_z [NN * EE];
__device__ float g_q [HH * NN * VV];
__device__ float g_k [HH * NN * VV];
__device__ float g_v [HH * NN * VV];
__device__ float g_o [NN * HV];
__device__ float g_an[NN * EE];
__device__ float g_h1[NN * E2];
__device__ float g_u [NN * EE];

// ---------------- packed f32x2 + async helpers ---------------------------------
__device__ __forceinline__ ull pk2(float x, float y) {
    ull u;
    asm("mov.b64 %0, {%1, %2};" : "=l"(u) : "f"(x), "f"(y));
    return u;
}
__device__ __forceinline__ void fma2(ull& c, ull a, ull b) {
    asm("fma.rn.f32x2 %0, %1, %2, %0;" : "+l"(c) : "l"(a), "l"(b));
}
__device__ __forceinline__ ull mul2(ull a, ull b) {
    ull d;
    asm("mul.rn.f32x2 %0, %1, %2;" : "=l"(d) : "l"(a), "l"(b));
    return d;
}
__device__ __forceinline__ float2 upk(ull u) {
    float x, y;
    asm("mov.b64 {%0, %1}, %2;" : "=f"(x), "=f"(y) : "l"(u));
    return make_float2(x, y);
}
__device__ __forceinline__ unsigned smem_u32(const void* p) {
    unsigned a;
    asm("{ .reg .u64 t; cvta.to.shared.u64 t, %1; cvt.u32.u64 %0, t; }"
        : "=r"(a) : "l"(p));
    return a;
}
__device__ __forceinline__ void cp16(unsigned dst, const void* src) {
    asm volatile("cp.async.cg.shared.global [%0], [%1], 16;"
                 :: "r"(dst), "l"(src) : "memory");
}
#define CP_COMMIT() asm volatile("cp.async.commit_group;" ::: "memory")
#define CP_WAIT0()  asm volatile("cp.async.wait_group 0;" ::: "memory")

// ------------------------------- embedding ------------------------------------
__global__ void embed_kernel(const int* __restrict__ ctx,
                             const float* __restrict__ table,
                             const float* __restrict__ pos) {
    int n = blockIdx.x;
    int t = threadIdx.x;
    int idx = ctx[n];
    const float4* tr = (const float4*)(table + (size_t)idx * EE);
    const float4* pr = (const float4*)(pos + (size_t)n * EE);
    float4* zr = (float4*)(g_z + (size_t)n * EE);
    float4 a = tr[t], b = pr[t];
    zr[t] = make_float4(a.x + b.x, a.y + b.y, a.z + b.z, a.w + b.w);
}

// ------------------------------- f32x2 GEMM (pipelined) ------------------------
// C[4096, NOUT] = A[4096, KTOT] @ B[KTOT, NOUT] (+bias)(+leaky)(+res).
// BM=BN=128, BK=16, 256 threads, 8x8 microtile. Double-buffered smem:
// B via cp.async (layout-preserving), A via reg prefetch + transposed STS.
// One __syncthreads per k-chunk; next chunk's loads overlap current compute.
template <int KTOT, int NOUT, bool HAS_BIAS, bool LEAKY, bool HAS_RES, bool QKV>
__device__ __forceinline__ void gemm_x2_core(const float* __restrict__ A,
                                             const float* __restrict__ B,
                                             const float* __restrict__ bias,
                                             const float* __restrict__ res,
                                             float* __restrict__ C) {
    __shared__ float As[2][16][132];   // [buf][k][m] transposed
    __shared__ float Bs[2][16][132];   // [buf][k][n]  (cp.async dest)

    int tid = threadIdx.x;
    int m0 = blockIdx.x * 128, n0 = blockIdx.y * 128;
    int tr = tid >> 4, tc = tid & 15;
    int rowA = tid >> 1, colA = (tid & 1) * 8;

    // B cp.async mapping: each thread moves two 16B chunks per k-chunk
    int bi0 = tid, bi1 = tid + 256;            // idx -> row=idx>>5, col4=(idx&31)*4
    int brow0 = bi0 >> 5, bc0 = (bi0 & 31) * 4;
    int brow1 = bi1 >> 5, bc1 = (bi1 & 31) * 4;

    ull acc[8][4];
#pragma unroll
    for (int i = 0; i < 8; i++)
#pragma unroll
        for (int j = 0; j < 4; j++) acc[i][j] = 0ull;

    float4 pa0, pa1;

    // ---- prologue: chunk 0
    {
        const float* s0;
        const float* s1;
        if (QKV) {
            int n = n0 + bc0; int h = n >> 5, v = n & 31;
            s0 = &B[((size_t)h * EE + brow0) * VV + v];
            n = n0 + bc1; h = n >> 5; v = n & 31;
            s1 = &B[((size_t)h * EE + brow1) * VV + v];
        } else {
            s0 = &B[(size_t)brow0 * NOUT + n0 + bc0];
            s1 = &B[(size_t)brow1 * NOUT + n0 + bc1];
        }
        cp16(smem_u32(&Bs[0][brow0][bc0]), s0);
        cp16(smem_u32(&Bs[0][brow1][bc1]), s1);
        CP_COMMIT();
        pa0 = *(const float4*)&A[(size_t)(m0 + rowA) * KTOT + colA];
        pa1 = *(const float4*)&A[(size_t)(m0 + rowA) * KTOT + colA + 4];
        As[0][colA + 0][rowA] = pa0.x; As[0][colA + 1][rowA] = pa0.y;
        As[0][colA + 2][rowA] = pa0.z; As[0][colA + 3][rowA] = pa0.w;
        As[0][colA + 4][rowA] = pa1.x; As[0][colA + 5][rowA] = pa1.y;
        As[0][colA + 6][rowA] = pa1.z; As[0][colA + 7][rowA] = pa1.w;
        CP_WAIT0();
        __syncthreads();
    }

    const int NC = KTOT / 16;
    for (int c = 0; c < NC; c++) {
        int buf = c & 1;
        if (c + 1 < NC) {
            int k0 = (c + 1) * 16;
            const float* s0;
            const float* s1;
            if (QKV) {
                int n = n0 + bc0; int h = n >> 5, v = n & 31;
                s0 = &B[((size_t)h * EE + k0 + brow0) * VV + v];
                n = n0 + bc1; h = n >> 5; v = n & 31;
                s1 = &B[((size_t)h * EE + k0 + brow1) * VV + v];
            } else {
                s0 = &B[(size_t)(k0 + brow0) * NOUT + n0 + bc0];
                s1 = &B[(size_t)(k0 + brow1) * NOUT + n0 + bc1];
            }
            cp16(smem_u32(&Bs[1 - buf][brow0][bc0]), s0);
            cp16(smem_u32(&Bs[1 - buf][brow1][bc1]), s1);
            CP_COMMIT();
            pa0 = *(const float4*)&A[(size_t)(m0 + rowA) * KTOT + k0 + colA];
            pa1 = *(const float4*)&A[(size_t)(m0 + rowA) * KTOT + k0 + colA + 4];
        }

#pragma unroll
        for (int kk = 0; kk < 16; kk++) {
            float4 a0 = *(const float4*)&As[buf][kk][tr * 8];
            float4 a1 = *(const float4*)&As[buf][kk][tr * 8 + 4];
            ull b0 = *(const ull*)&Bs[buf][kk][tc * 8 + 0];
            ull b1 = *(const ull*)&Bs[buf][kk][tc * 8 + 2];
            ull b2 = *(const ull*)&Bs[buf][kk][tc * 8 + 4];
            ull b3 = *(const ull*)&Bs[buf][kk][tc * 8 + 6];
            ull ap[8];
            ap[0] = pk2(a0.x, a0.x); ap[1] = pk2(a0.y, a0.y);
            ap[2] = pk2(a0.z, a0.z); ap[3] = pk2(a0.w, a0.w);
            ap[4] = pk2(a1.x, a1.x); ap[5] = pk2(a1.y, a1.y);
            ap[6] = pk2(a1.z, a1.z); ap[7] = pk2(a1.w, a1.w);
#pragma unroll
            for (int i = 0; i < 8; i++) {
                fma2(acc[i][0], ap[i], b0);
                fma2(acc[i][1], ap[i], b1);
                fma2(acc[i][2], ap[i], b2);
                fma2(acc[i][3], ap[i], b3);
            }
        }

        if (c + 1 < NC) {
            // other buffer; its readers (compute c-1) finished before this
            // iteration's entry sync
            As[1 - buf][colA + 0][rowA] = pa0.x; As[1 - buf][colA + 1][rowA] = pa0.y;
            As[1 - buf][colA + 2][rowA] = pa0.z; As[1 - buf][colA + 3][rowA] = pa0.w;
            As[1 - buf][colA + 4][rowA] = pa1.x; As[1 - buf][colA + 5][rowA] = pa1.y;
            As[1 - buf][colA + 6][rowA] = pa1.z; As[1 - buf][colA + 7][rowA] = pa1.w;
            CP_WAIT0();
            __syncthreads();
        }
    }

#pragma unroll
    for (int i = 0; i < 8; i++) {
        size_t row = (size_t)(m0 + tr * 8 + i);
        int col = n0 + tc * 8;
        float v[8];
#pragma unroll
        for (int j = 0; j < 4; j++) {
            float2 t = upk(acc[i][j]);
            v[2 * j] = t.x; v[2 * j + 1] = t.y;
        }
        if (HAS_BIAS) {
#pragma unroll
            for (int j = 0; j < 8; j++) v[j] += bias[col + j];
        }
        if (LEAKY) {
#pragma unroll
            for (int j = 0; j < 8; j++) v[j] = v[j] >= 0.f ? v[j] : 0.01f * v[j];
        }
        if (QKV) {
            int h = col >> 5, vv = col & 31;
            float* dst = C + (size_t)h * NN * VV + row * VV + vv;
            *(float4*)dst = make_float4(v[0], v[1], v[2], v[3]);
            *(float4*)(dst + 4) = make_float4(v[4], v[5], v[6], v[7]);
        } else {
            if (HAS_RES) {
                float4 r0 = *(const float4*)&res[row * NOUT + col];
                float4 r1 = *(const float4*)&res[row * NOUT + col + 4];
                v[0] += r0.x; v[1] += r0.y; v[2] += r0.z; v[3] += r0.w;
                v[4] += r1.x; v[5] += r1.y; v[6] += r1.z; v[7] += r1.w;
            }
            *(float4*)&C[row * NOUT + col] = make_float4(v[0], v[1], v[2], v[3]);
            *(float4*)&C[row * NOUT + col + 4] = make_float4(v[4], v[5], v[6], v[7]);
        }
    }
}

__global__ __launch_bounds__(256, 1) void qkv_x2(const float* __restrict__ Wq,
                                                 const float* __restrict__ Wk,
                                                 const float* __restrict__ Wv,
                                                 int layer) {
    int which = blockIdx.z;
    const float* W = (which == 0 ? Wq : which == 1 ? Wk : Wv)
                     + (size_t)layer * HH * EE * VV;
    float* outp = which == 0 ? g_q : which == 1 ? g_k : g_v;
    gemm_x2_core<EE, HV, false, false, false, true>(g_z, W, nullptr, nullptr, outp);
}
__global__ __launch_bounds__(256, 1) void wo_x2(const float* __restrict__ B) {
    gemm_x2_core<HV, EE, false, false, true, false>(g_o, B, nullptr, g_z, g_u);
}
__global__ __launch_bounds__(256, 1) void ff1_x2(const float* __restrict__ B,
                                                 const float* __restrict__ bias) {
    gemm_x2_core<EE, E2, true, true, false, false>(g_an, B, bias, nullptr, g_h1);
}
__global__ __launch_bounds__(256, 1) void ff2_x2(const float* __restrict__ B,
                                                 const float* __restrict__ bias) {
    gemm_x2_core<E2, EE, true, false, true, false>(g_h1, B, bias, g_an, g_u);
}

// ------------------------------- flash attention -------------------------------
// Per block: one head, 64 queries, 64-key tiles. In-register online softmax;
// K/V for tile kt+1 prefetched to regs right after tile kt's STS so LDG
// latency hides behind the S/softmax/PV body.
__global__ __launch_bounds__(256) void attn_kernel() {
    __shared__ float Qs[32][68];     // [d][q], pre-scaled
    __shared__ float Ks[32][68];     // [d][key]
    __shared__ float Vs[64][36];     // [key][d]
    __shared__ float Psh[64][68];    // P transposed: [key][q]
    int tid = threadIdx.x;
    int h = blockIdx.y;
    int q0 = blockIdx.x * 64;
    const float scale = 0.17677669529663687f;  // 1/sqrt(32)
    int r8 = tid >> 3;
    int c4 = (tid & 7) * 4;
    const float* qb = g_q + (size_t)h * NN * VV;
    const float* kb = g_k + (size_t)h * NN * VV;
    const float* vb = g_v + (size_t)h * NN * VV;
    {
        float4 qa = *(const float4*)&qb[(size_t)(q0 + r8) * VV + c4];
        float4 qc = *(const float4*)&qb[(size_t)(q0 + r8 + 32) * VV + c4];
        Qs[c4 + 0][r8] = qa.x * scale; Qs[c4 + 1][r8] = qa.y * scale;
        Qs[c4 + 2][r8] = qa.z * scale; Qs[c4 + 3][r8] = qa.w * scale;
        Qs[c4 + 0][r8 + 32] = qc.x * scale; Qs[c4 + 1][r8 + 32] = qc.y * scale;
        Qs[c4 + 2][r8 + 32] = qc.z * scale; Qs[c4 + 3][r8 + 32] = qc.w * scale;
    }
    int tr = tid >> 4;             // q rows tr*4+i
    int tc = tid & 15;             // keys tc*4+j (S); d-pair tc*2 (PV/out)
    int sq = tr * 4, sk = tc * 4;
    float m[4], l[4];
#pragma unroll
    for (int i = 0; i < 4; i++) { m[i] = -INFINITY; l[i] = 0.f; }
    ull oacc[4] = {0ull, 0ull, 0ull, 0ull};

    // prefetch tile 0
    float4 ka = *(const float4*)&kb[(size_t)r8 * VV + c4];
    float4 kc = *(const float4*)&kb[(size_t)(r8 + 32) * VV + c4];
    float4 va = *(const float4*)&vb[(size_t)r8 * VV + c4];
    float4 vc = *(const float4*)&vb[(size_t)(r8 + 32) * VV + c4];

    const int NT = NN / 64;
    for (int kt = 0; kt < NT; kt++) {
        __syncthreads();   // prior PV done with Vs/Psh (also orders Qs writes)
        Ks[c4 + 0][r8] = ka.x; Ks[c4 + 1][r8] = ka.y;
        Ks[c4 + 2][r8] = ka.z; Ks[c4 + 3][r8] = ka.w;
        Ks[c4 + 0][r8 + 32] = kc.x; Ks[c4 + 1][r8 + 32] = kc.y;
        Ks[c4 + 2][r8 + 32] = kc.z; Ks[c4 + 3][r8 + 32] = kc.w;
        *(float4*)&Vs[r8][c4] = va;
        *(float4*)&Vs[r8 + 32][c4] = vc;
        __syncthreads();

        if (kt + 1 < NT) {   // prefetch next tile; hides behind S/softmax/PV
            int k0 = (kt + 1) * 64;
            ka = *(const float4*)&kb[(size_t)(k0 + r8) * VV + c4];
            kc = *(const float4*)&kb[(size_t)(k0 + r8 + 32) * VV + c4];
            va = *(const float4*)&vb[(size_t)(k0 + r8) * VV + c4];
            vc = *(const float4*)&vb[(size_t)(k0 + r8 + 32) * VV + c4];
        }

        // S = Q K^T : 4 query rows x 2 packed key-pairs (f32x2)
        ull sp[4][2];
#pragma unroll
        for (int i = 0; i < 4; i++) { sp[i][0] = 0ull; sp[i][1] = 0ull; }
#pragma unroll 8
        for (int d = 0; d < 32; d++) {
            float4 a = *(const float4*)&Qs[d][sq];
            float4 b = *(const float4*)&Ks[d][sk];
            ull bp0 = pk2(b.x, b.y), bp1 = pk2(b.z, b.w);
            ull ap0 = pk2(a.x, a.x), ap1 = pk2(a.y, a.y);
            ull ap2 = pk2(a.z, a.z), ap3 = pk2(a.w, a.w);
            fma2(sp[0][0], ap0, bp0); fma2(sp[0][1], ap0, bp1);
            fma2(sp[1][0], ap1, bp0); fma2(sp[1][1], ap1, bp1);
            fma2(sp[2][0], ap2, bp0); fma2(sp[2][1], ap2, bp1);
            fma2(sp[3][0], ap3, bp0); fma2(sp[3][1], ap3, bp1);
        }
        float s[4][4];
#pragma unroll
        for (int i = 0; i < 4; i++) {
            float2 t0 = upk(sp[i][0]), t1 = upk(sp[i][1]);
            s[i][0] = t0.x; s[i][1] = t0.y; s[i][2] = t1.x; s[i][3] = t1.y;
        }

        // in-register online softmax (per q-row, reduce over 16 lanes = 64 keys)
        float corr[4];
#pragma unroll
        for (int i = 0; i < 4; i++) {
            float mx = fmaxf(fmaxf(s[i][0], s[i][1]), fmaxf(s[i][2], s[i][3]));
            mx = fmaxf(mx, __shfl_xor_sync(0xffffffffu, mx, 1));
            mx = fmaxf(mx, __shfl_xor_sync(0xffffffffu, mx, 2));
            mx = fmaxf(mx, __shfl_xor_sync(0xffffffffu, mx, 4));
            mx = fmaxf(mx, __shfl_xor_sync(0xffffffffu, mx, 8));
            float mnew = fmaxf(m[i], mx);
            float p0 = __expf(s[i][0] - mnew);
            float p1 = __expf(s[i][1] - mnew);
            float p2 = __expf(s[i][2] - mnew);
            float p3 = __expf(s[i][3] - mnew);
            s[i][0] = p0; s[i][1] = p1; s[i][2] = p2; s[i][3] = p3;
            float sum = (p0 + p1) + (p2 + p3);
            sum += __shfl_xor_sync(0xffffffffu, sum, 1);
            sum += __shfl_xor_sync(0xffffffffu, sum, 2);
            sum += __shfl_xor_sync(0xffffffffu, sum, 4);
            sum += __shfl_xor_sync(0xffffffffu, sum, 8);
            float cr = __expf(m[i] - mnew);
            corr[i] = cr;
            l[i] = l[i] * cr + sum;
            m[i] = mnew;
        }
        oacc[0] = mul2(oacc[0], pk2(corr[0], corr[0]));
        oacc[1] = mul2(oacc[1], pk2(corr[1], corr[1]));
        oacc[2] = mul2(oacc[2], pk2(corr[2], corr[2]));
        oacc[3] = mul2(oacc[3], pk2(corr[3], corr[3]));

        // exchange P through smem (transposed for PV)
#pragma unroll
        for (int j = 0; j < 4; j++)
            *(float4*)&Psh[sk + j][sq] = make_float4(s[0][j], s[1][j], s[2][j], s[3][j]);
        __syncthreads();

        // O += P @ V   (rows tr*4+i, packed d pair tc*2)
#pragma unroll 8
        for (int kj = 0; kj < 64; kj++) {
            float4 p = *(const float4*)&Psh[kj][sq];
            ull vvp = *(const ull*)&Vs[kj][tc * 2];
            fma2(oacc[0], pk2(p.x, p.x), vvp);
            fma2(oacc[1], pk2(p.y, p.y), vvp);
            fma2(oacc[2], pk2(p.z, p.z), vvp);
            fma2(oacc[3], pk2(p.w, p.w), vvp);
        }
    }
#pragma unroll
    for (int i = 0; i < 4; i++) {
        float inv = 1.f / l[i];
        float2 t = upk(oacc[i]);
        *(float2*)&g_o[(size_t)(q0 + tr * 4 + i) * HV + h * VV + tc * 2] =
            make_float2(t.x * inv, t.y * inv);
    }
}

// ------------------------------- layernorm ------------------------------------
// mean over E, unbiased std (ddof=1), NO eps. One block (256 thr) per row.
__device__ __forceinline__ void ln_core(const float* __restrict__ in,
                                        float* __restrict__ out) {
    __shared__ float reds[8];
    __shared__ float redv[8];
    int r = blockIdx.x, tid = threadIdx.x;
    const float4* x = (const float4*)(in + (size_t)r * EE);
    float4 v = x[tid];
    float s = (v.x + v.y) + (v.z + v.w);
#pragma unroll
    for (int o = 16; o > 0; o >>= 1) s += __shfl_xor_sync(0xffffffffu, s, o);
    if ((tid & 31) == 0) reds[tid >> 5] = s;
    __syncthreads();
    float tot = ((reds[0] + reds[1]) + (reds[2] + reds[3]))
              + ((reds[4] + reds[5]) + (reds[6] + reds[7]));
    float mean = tot * (1.f / 1024.f);
    float dx = v.x - mean, dy = v.y - mean, dz = v.z - mean, dw = v.w - mean;
    float d = (dx * dx + dy * dy) + (dz * dz + dw * dw);
#pragma unroll
    for (int o = 16; o > 0; o >>= 1) d += __shfl_xor_sync(0xffffffffu, d, o);
    if ((tid & 31) == 0) redv[tid >> 5] = d;
    __syncthreads();
    float var = ((redv[0] + redv[1]) + (redv[2] + redv[3]))
              + ((redv[4] + redv[5]) + (redv[6] + redv[7]));
    float rstd = 1.f / sqrtf(var * (1.f / 1023.f));
    float4* o4 = (float4*)(out + (size_t)r * EE);
    o4[tid] = make_float4(dx * rstd, dy * rstd, dz * rstd, dw * rstd);
}

__global__ __launch_bounds__(256) void ln_an_kernel() { ln_core(g_u, g_an); }
__global__ __launch_bounds__(256) void ln_z_kernel() { ln_core(g_u, g_z); }
__global__ __launch_bounds__(256) void ln_out_kernel(float* out) { ln_core(g_u, out); }

// ------------------------------- driver ---------------------------------------
extern "C" void kernel_launch(void* const* d_in, const int* in_sizes, int n_in,
                              void* d_out, int out_size) {
    const int*   context = (const int*)d_in[0];
    const float* table   = (const float*)d_in[1];
    const float* pos     = (const float*)d_in[2];
    const float* Wq      = (const float*)d_in[3];
    const float* Wk      = (const float*)d_in[4];
    const float* Wv      = (const float*)d_in[5];
    const float* Wo      = (const float*)d_in[6];
    const float* W1      = (const float*)d_in[7];
    const float* b1      = (const float*)d_in[8];
    const float* W2      = (const float*)d_in[9];
    const float* b2      = (const float*)d_in[10];
    float* out = (float*)d_out;

    embed_kernel<<<NN, 256>>>(context, table, pos);
    for (int l = 0; l < LL; l++) {
        qkv_x2<<<dim3(NN / 128, HV / 128, 3), 256>>>(Wq, Wk, Wv, l);
        attn_kernel<<<dim3(NN / 64, HH), 256>>>();
        wo_x2<<<dim3(NN / 128, EE / 128), 256>>>(Wo + (size_t)l * HV * EE);
        ln_an_kernel<<<NN, 256>>>();
        ff1_x2<<<dim3(NN / 128, E2 / 128), 256>>>(W1 + (size_t)l * EE * E2,
                                                  b1 + (size_t)l * E2);
        ff2_x2<<<dim3(NN / 128, EE / 128), 256>>>(W2 + (size_t)l * E2 * EE,
                                                  b2 + (size_t)l * EE);
        if (l == LL - 1) ln_out_kernel<<<NN, 256>>>(out);
        else             ln_z_kernel<<<NN, 256>>>();
    }
}

// round 12
// speedup vs baseline: 1.0092x; 1.0092x over previous
#include <cuda_runtime.h>
#include <math.h>

#define NN 4096
#define EE 1024
#define HH 16
#define VV 32
#define LL 6
#define HV 512
#define E2 2048

typedef unsigned long long ull;

// ---------------- scratch (static device globals; no allocations) -------------
__device__ float g_z [NN * EE];
__device__ float g_q [HH * NN * VV];
__device__ float g_k [HH * NN * VV];
__device__ float g_v [HH * NN * VV];
__device__ float g_o [NN * HV];
__device__ float g_an[NN * EE];
__device__ float g_h1[NN * E2];
__device__ float g_u [NN * EE];

// ---------------- packed f32x2 helpers -----------------------------------------
__device__ __forceinline__ ull pk2(float x, float y) {
    ull u;
    asm("mov.b64 %0, {%1, %2};" : "=l"(u) : "f"(x), "f"(y));
    return u;
}
__device__ __forceinline__ void fma2(ull& c, ull a, ull b) {
    asm("fma.rn.f32x2 %0, %1, %2, %0;" : "+l"(c) : "l"(a), "l"(b));
}
__device__ __forceinline__ ull mul2(ull a, ull b) {
    ull d;
    asm("mul.rn.f32x2 %0, %1, %2;" : "=l"(d) : "l"(a), "l"(b));
    return d;
}
__device__ __forceinline__ float2 upk(ull u) {
    float x, y;
    asm("mov.b64 {%0, %1}, %2;" : "=f"(x), "=f"(y) : "l"(u));
    return make_float2(x, y);
}

// ------------------------------- embedding ------------------------------------
__global__ void embed_kernel(const int* __restrict__ ctx,
                             const float* __restrict__ table,
                             const float* __restrict__ pos) {
    int n = blockIdx.x;
    int t = threadIdx.x;
    int idx = ctx[n];
    const float4* tr = (const float4*)(table + (size_t)idx * EE);
    const float4* pr = (const float4*)(pos + (size_t)n * EE);
    float4* zr = (float4*)(g_z + (size_t)n * EE);
    float4 a = tr[t], b = pr[t];
    zr[t] = make_float4(a.x + b.x, a.y + b.y, a.z + b.z, a.w + b.w);
}

// ------------------------------- f32x2 GEMM (R10 core: at the FFMA wall) -------
// C[4096, NOUT] = A[4096, KTOT] @ B[KTOT, NOUT] (+bias)(+leaky)(+res).
// BM=BN=128, BK=16, 256 threads, 8x8 microtile as 8 rows x 4 packed col-pairs.
// Single-buffered: 2 CTAs/SM give the cross-CTA overlap; chunk compute
// (~4k cyc) dwarfs LDG latency (~600 cyc), so no deeper pipeline is needed.
template <int KTOT, int NOUT, bool HAS_BIAS, bool LEAKY, bool HAS_RES, bool QKV>
__device__ __forceinline__ void gemm_x2_core(const float* __restrict__ A,
                                             const float* __restrict__ B,
                                             const float* __restrict__ bias,
                                             const float* __restrict__ res,
                                             float* __restrict__ C) {
    __shared__ float As[16][132];   // [k][m] transposed
    __shared__ float Bs[16][132];   // [k][n]

    int tid = threadIdx.x;
    int m0 = blockIdx.x * 128, n0 = blockIdx.y * 128;
    int tr = tid >> 4, tc = tid & 15;
    int rowA = tid >> 1, colA = (tid & 1) * 8;
    int rowB = tid >> 4, colB = (tid & 15) * 8;

    ull acc[8][4];
#pragma unroll
    for (int i = 0; i < 8; i++)
#pragma unroll
        for (int j = 0; j < 4; j++) acc[i][j] = 0ull;

    for (int k0 = 0; k0 < KTOT; k0 += 16) {
        float4 a0g = *(const float4*)&A[(size_t)(m0 + rowA) * KTOT + k0 + colA];
        float4 a1g = *(const float4*)&A[(size_t)(m0 + rowA) * KTOT + k0 + colA + 4];
        float4 b0g, b1g;
        {
            int kk = k0 + rowB;
            if (QKV) {
                int n = n0 + colB;
                int h = n >> 5, v = n & 31;
                b0g = *(const float4*)&B[((size_t)h * EE + kk) * VV + v];
                b1g = *(const float4*)&B[((size_t)h * EE + kk) * VV + v + 4];
            } else {
                b0g = *(const float4*)&B[(size_t)kk * NOUT + n0 + colB];
                b1g = *(const float4*)&B[(size_t)kk * NOUT + n0 + colB + 4];
            }
        }
        __syncthreads();
        As[colA + 0][rowA] = a0g.x; As[colA + 1][rowA] = a0g.y;
        As[colA + 2][rowA] = a0g.z; As[colA + 3][rowA] = a0g.w;
        As[colA + 4][rowA] = a1g.x; As[colA + 5][rowA] = a1g.y;
        As[colA + 6][rowA] = a1g.z; As[colA + 7][rowA] = a1g.w;
        *(float4*)&Bs[rowB][colB] = b0g;
        *(float4*)&Bs[rowB][colB + 4] = b1g;
        __syncthreads();
#pragma unroll
        for (int kk = 0; kk < 16; kk++) {
            float4 a0 = *(const float4*)&As[kk][tr * 8];
            float4 a1 = *(const float4*)&As[kk][tr * 8 + 4];
            ull b0 = *(const ull*)&Bs[kk][tc * 8 + 0];
            ull b1 = *(const ull*)&Bs[kk][tc * 8 + 2];
            ull b2 = *(const ull*)&Bs[kk][tc * 8 + 4];
            ull b3 = *(const ull*)&Bs[kk][tc * 8 + 6];
            ull ap[8];
            ap[0] = pk2(a0.x, a0.x); ap[1] = pk2(a0.y, a0.y);
            ap[2] = pk2(a0.z, a0.z); ap[3] = pk2(a0.w, a0.w);
            ap[4] = pk2(a1.x, a1.x); ap[5] = pk2(a1.y, a1.y);
            ap[6] = pk2(a1.z, a1.z); ap[7] = pk2(a1.w, a1.w);
#pragma unroll
            for (int i = 0; i < 8; i++) {
                fma2(acc[i][0], ap[i], b0);
                fma2(acc[i][1], ap[i], b1);
                fma2(acc[i][2], ap[i], b2);
                fma2(acc[i][3], ap[i], b3);
            }
        }
    }

#pragma unroll
    for (int i = 0; i < 8; i++) {
        size_t row = (size_t)(m0 + tr * 8 + i);
        int col = n0 + tc * 8;
        float v[8];
#pragma unroll
        for (int j = 0; j < 4; j++) {
            float2 t = upk(acc[i][j]);
            v[2 * j] = t.x; v[2 * j + 1] = t.y;
        }
        if (HAS_BIAS) {
#pragma unroll
            for (int j = 0; j < 8; j++) v[j] += bias[col + j];
        }
        if (LEAKY) {
#pragma unroll
            for (int j = 0; j < 8; j++) v[j] = v[j] >= 0.f ? v[j] : 0.01f * v[j];
        }
        if (QKV) {
            int h = col >> 5, vv = col & 31;
            float* dst = C + (size_t)h * NN * VV + row * VV + vv;
            *(float4*)dst = make_float4(v[0], v[1], v[2], v[3]);
            *(float4*)(dst + 4) = make_float4(v[4], v[5], v[6], v[7]);
        } else {
            if (HAS_RES) {
                float4 r0 = *(const float4*)&res[row * NOUT + col];
                float4 r1 = *(const float4*)&res[row * NOUT + col + 4];
                v[0] += r0.x; v[1] += r0.y; v[2] += r0.z; v[3] += r0.w;
                v[4] += r1.x; v[5] += r1.y; v[6] += r1.z; v[7] += r1.w;
            }
            *(float4*)&C[row * NOUT + col] = make_float4(v[0], v[1], v[2], v[3]);
            *(float4*)&C[row * NOUT + col + 4] = make_float4(v[4], v[5], v[6], v[7]);
        }
    }
}

__global__ __launch_bounds__(256, 1) void qkv_x2(const float* __restrict__ Wq,
                                                 const float* __restrict__ Wk,
                                                 const float* __restrict__ Wv,
                                                 int layer) {
    int which = blockIdx.z;
    const float* W = (which == 0 ? Wq : which == 1 ? Wk : Wv)
                     + (size_t)layer * HH * EE * VV;
    float* outp = which == 0 ? g_q : which == 1 ? g_k : g_v;
    gemm_x2_core<EE, HV, false, false, false, true>(g_z, W, nullptr, nullptr, outp);
}
__global__ __launch_bounds__(256, 1) void wo_x2(const float* __restrict__ B) {
    gemm_x2_core<HV, EE, false, false, true, false>(g_o, B, nullptr, g_z, g_u);
}
__global__ __launch_bounds__(256, 1) void ff1_x2(const float* __restrict__ B,
                                                 const float* __restrict__ bias) {
    gemm_x2_core<EE, E2, true, true, false, false>(g_an, B, bias, nullptr, g_h1);
}
__global__ __launch_bounds__(256, 1) void ff2_x2(const float* __restrict__ B,
                                                 const float* __restrict__ bias) {
    gemm_x2_core<E2, EE, true, false, true, false>(g_h1, B, bias, g_an, g_u);
}

// ------------------------------- flash attention (R11 variant: K/V prefetch) ---
// Per block: one head, 64 queries, 64-key tiles. In-register online softmax;
// K/V for tile kt+1 prefetched to regs right after tile kt's STS so LDG
// latency hides behind the S/softmax/PV body.
__global__ __launch_bounds__(256) void attn_kernel() {
    __shared__ float Qs[32][68];     // [d][q], pre-scaled
    __shared__ float Ks[32][68];     // [d][key]
    __shared__ float Vs[64][36];     // [key][d]
    __shared__ float Psh[64][68];    // P transposed: [key][q]
    int tid = threadIdx.x;
    int h = blockIdx.y;
    int q0 = blockIdx.x * 64;
    const float scale = 0.17677669529663687f;  // 1/sqrt(32)
    int r8 = tid >> 3;
    int c4 = (tid & 7) * 4;
    const float* qb = g_q + (size_t)h * NN * VV;
    const float* kb = g_k + (size_t)h * NN * VV;
    const float* vb = g_v + (size_t)h * NN * VV;
    {
        float4 qa = *(const float4*)&qb[(size_t)(q0 + r8) * VV + c4];
        float4 qc = *(const float4*)&qb[(size_t)(q0 + r8 + 32) * VV + c4];
        Qs[c4 + 0][r8] = qa.x * scale; Qs[c4 + 1][r8] = qa.y * scale;
        Qs[c4 + 2][r8] = qa.z * scale; Qs[c4 + 3][r8] = qa.w * scale;
        Qs[c4 + 0][r8 + 32] = qc.x * scale; Qs[c4 + 1][r8 + 32] = qc.y * scale;
        Qs[c4 + 2][r8 + 32] = qc.z * scale; Qs[c4 + 3][r8 + 32] = qc.w * scale;
    }
    int tr = tid >> 4;             // q rows tr*4+i
    int tc = tid & 15;             // keys tc*4+j (S); d-pair tc*2 (PV/out)
    int sq = tr * 4, sk = tc * 4;
    float m[4], l[4];
#pragma unroll
    for (int i = 0; i < 4; i++) { m[i] = -INFINITY; l[i] = 0.f; }
    ull oacc[4] = {0ull, 0ull, 0ull, 0ull};

    // prefetch tile 0
    float4 ka = *(const float4*)&kb[(size_t)r8 * VV + c4];
    float4 kc = *(const float4*)&kb[(size_t)(r8 + 32) * VV + c4];
    float4 va = *(const float4*)&vb[(size_t)r8 * VV + c4];
    float4 vc = *(const float4*)&vb[(size_t)(r8 + 32) * VV + c4];

    const int NT = NN / 64;
    for (int kt = 0; kt < NT; kt++) {
        __syncthreads();   // prior PV done with Vs/Psh (also orders Qs writes)
        Ks[c4 + 0][r8] = ka.x; Ks[c4 + 1][r8] = ka.y;
        Ks[c4 + 2][r8] = ka.z; Ks[c4 + 3][r8] = ka.w;
        Ks[c4 + 0][r8 + 32] = kc.x; Ks[c4 + 1][r8 + 32] = kc.y;
        Ks[c4 + 2][r8 + 32] = kc.z; Ks[c4 + 3][r8 + 32] = kc.w;
        *(float4*)&Vs[r8][c4] = va;
        *(float4*)&Vs[r8 + 32][c4] = vc;
        __syncthreads();

        if (kt + 1 < NT) {   // prefetch next tile; hides behind S/softmax/PV
            int k0 = (kt + 1) * 64;
            ka = *(const float4*)&kb[(size_t)(k0 + r8) * VV + c4];
            kc = *(const float4*)&kb[(size_t)(k0 + r8 + 32) * VV + c4];
            va = *(const float4*)&vb[(size_t)(k0 + r8) * VV + c4];
            vc = *(const float4*)&vb[(size_t)(k0 + r8 + 32) * VV + c4];
        }

        // S = Q K^T : 4 query rows x 2 packed key-pairs (f32x2)
        ull sp[4][2];
#pragma unroll
        for (int i = 0; i < 4; i++) { sp[i][0] = 0ull; sp[i][1] = 0ull; }
#pragma unroll 8
        for (int d = 0; d < 32; d++) {
            float4 a = *(const float4*)&Qs[d][sq];
            float4 b = *(const float4*)&Ks[d][sk];
            ull bp0 = pk2(b.x, b.y), bp1 = pk2(b.z, b.w);
            ull ap0 = pk2(a.x, a.x), ap1 = pk2(a.y, a.y);
            ull ap2 = pk2(a.z, a.z), ap3 = pk2(a.w, a.w);
            fma2(sp[0][0], ap0, bp0); fma2(sp[0][1], ap0, bp1);
            fma2(sp[1][0], ap1, bp0); fma2(sp[1][1], ap1, bp1);
            fma2(sp[2][0], ap2, bp0); fma2(sp[2][1], ap2, bp1);
            fma2(sp[3][0], ap3, bp0); fma2(sp[3][1], ap3, bp1);
        }
        float s[4][4];
#pragma unroll
        for (int i = 0; i < 4; i++) {
            float2 t0 = upk(sp[i][0]), t1 = upk(sp[i][1]);
            s[i][0] = t0.x; s[i][1] = t0.y; s[i][2] = t1.x; s[i][3] = t1.y;
        }

        // in-register online softmax (per q-row, reduce over 16 lanes = 64 keys)
        float corr[4];
#pragma unroll
        for (int i = 0; i < 4; i++) {
            float mx = fmaxf(fmaxf(s[i][0], s[i][1]), fmaxf(s[i][2], s[i][3]));
            mx = fmaxf(mx, __shfl_xor_sync(0xffffffffu, mx, 1));
            mx = fmaxf(mx, __shfl_xor_sync(0xffffffffu, mx, 2));
            mx = fmaxf(mx, __shfl_xor_sync(0xffffffffu, mx, 4));
            mx = fmaxf(mx, __shfl_xor_sync(0xffffffffu, mx, 8));
            float mnew = fmaxf(m[i], mx);
            float p0 = __expf(s[i][0] - mnew);
            float p1 = __expf(s[i][1] - mnew);
            float p2 = __expf(s[i][2] - mnew);
            float p3 = __expf(s[i][3] - mnew);
            s[i][0] = p0; s[i][1] = p1; s[i][2] = p2; s[i][3] = p3;
            float sum = (p0 + p1) + (p2 + p3);
            sum += __shfl_xor_sync(0xffffffffu, sum, 1);
            sum += __shfl_xor_sync(0xffffffffu, sum, 2);
            sum += __shfl_xor_sync(0xffffffffu, sum, 4);
            sum += __shfl_xor_sync(0xffffffffu, sum, 8);
            float cr = __expf(m[i] - mnew);
            corr[i] = cr;
            l[i] = l[i] * cr + sum;
            m[i] = mnew;
        }
        oacc[0] = mul2(oacc[0], pk2(corr[0], corr[0]));
        oacc[1] = mul2(oacc[1], pk2(corr[1], corr[1]));
        oacc[2] = mul2(oacc[2], pk2(corr[2], corr[2]));
        oacc[3] = mul2(oacc[3], pk2(corr[3], corr[3]));

        // exchange P through smem (transposed for PV)
#pragma unroll
        for (int j = 0; j < 4; j++)
            *(float4*)&Psh[sk + j][sq] = make_float4(s[0][j], s[1][j], s[2][j], s[3][j]);
        __syncthreads();

        // O += P @ V   (rows tr*4+i, packed d pair tc*2)
#pragma unroll 8
        for (int kj = 0; kj < 64; kj++) {
            float4 p = *(const float4*)&Psh[kj][sq];
            ull vvp = *(const ull*)&Vs[kj][tc * 2];
            fma2(oacc[0], pk2(p.x, p.x), vvp);
            fma2(oacc[1], pk2(p.y, p.y), vvp);
            fma2(oacc[2], pk2(p.z, p.z), vvp);
            fma2(oacc[3], pk2(p.w, p.w), vvp);
        }
    }
#pragma unroll
    for (int i = 0; i < 4; i++) {
        float inv = 1.f / l[i];
        float2 t = upk(oacc[i]);
        *(float2*)&g_o[(size_t)(q0 + tr * 4 + i) * HV + h * VV + tc * 2] =
            make_float2(t.x * inv, t.y * inv);
    }
}

// ------------------------------- layernorm ------------------------------------
// mean over E, unbiased std (ddof=1), NO eps. One block (256 thr) per row.
__device__ __forceinline__ void ln_core(const float* __restrict__ in,
                                        float* __restrict__ out) {
    __shared__ float reds[8];
    __shared__ float redv[8];
    int r = blockIdx.x, tid = threadIdx.x;
    const float4* x = (const float4*)(in + (size_t)r * EE);
    float4 v = x[tid];
    float s = (v.x + v.y) + (v.z + v.w);
#pragma unroll
    for (int o = 16; o > 0; o >>= 1) s += __shfl_xor_sync(0xffffffffu, s, o);
    if ((tid & 31) == 0) reds[tid >> 5] = s;
    __syncthreads();
    float tot = ((reds[0] + reds[1]) + (reds[2] + reds[3]))
              + ((reds[4] + reds[5]) + (reds[6] + reds[7]));
    float mean = tot * (1.f / 1024.f);
    float dx = v.x - mean, dy = v.y - mean, dz = v.z - mean, dw = v.w - mean;
    float d = (dx * dx + dy * dy) + (dz * dz + dw * dw);
#pragma unroll
    for (int o = 16; o > 0; o >>= 1) d += __shfl_xor_sync(0xffffffffu, d, o);
    if ((tid & 31) == 0) redv[tid >> 5] = d;
    __syncthreads();
    float var = ((redv[0] + redv[1]) + (redv[2] + redv[3]))
              + ((redv[4] + redv[5]) + (redv[6] + redv[7]));
    float rstd = 1.f / sqrtf(var * (1.f / 1023.f));
    float4* o4 = (float4*)(out + (size_t)r * EE);
    o4[tid] = make_float4(dx * rstd, dy * rstd, dz * rstd, dw * rstd);
}

__global__ __launch_bounds__(256) void ln_an_kernel() { ln_core(g_u, g_an); }
__global__ __launch_bounds__(256) void ln_z_kernel() { ln_core(g_u, g_z); }
__global__ __launch_bounds__(256) void ln_out_kernel(float* out) { ln_core(g_u, out); }

// ------------------------------- driver ---------------------------------------
extern "C" void kernel_launch(void* const* d_in, const int* in_sizes, int n_in,
                              void* d_out, int out_size) {
    const int*   context = (const int*)d_in[0];
    const float* table   = (const float*)d_in[1];
    const float* pos     = (const float*)d_in[2];
    const float* Wq      = (const float*)d_in[3];
    const float* Wk      = (const float*)d_in[4];
    const float* Wv      = (const float*)d_in[5];
    const float* Wo      = (const float*)d_in[6];
    const float* W1      = (const float*)d_in[7];
    const float* b1      = (const float*)d_in[8];
    const float* W2      = (const float*)d_in[9];
    const float* b2      = (const float*)d_in[10];
    float* out = (float*)d_out;

    embed_kernel<<<NN, 256>>>(context, table, pos);
    for (int l = 0; l < LL; l++) {
        qkv_x2<<<dim3(NN / 128, HV / 128, 3), 256>>>(Wq, Wk, Wv, l);
        attn_kernel<<<dim3(NN / 64, HH), 256>>>();
        wo_x2<<<dim3(NN / 128, EE / 128), 256>>>(Wo + (size_t)l * HV * EE);
        ln_an_kernel<<<NN, 256>>>();
        ff1_x2<<<dim3(NN / 128, E2 / 128), 256>>>(W1 + (size_t)l * EE * E2,
                                                  b1 + (size_t)l * E2);
        ff2_x2<<<dim3(NN / 128, EE / 128), 256>>>(W2 + (size_t)l * E2 * EE,
                                                  b2 + (size_t)l * EE);
        if (l == LL - 1) ln_out_kernel<<<NN, 256>>>(out);
        else             ln_z_kernel<<<NN, 256>>>();
    }
}